// round 12
// baseline (speedup 1.0000x reference)
#include <cuda_runtime.h>
#include <cstdint>

// ---------------------------------------------------------------------------
// EdgeDecoder: per-edge 3-layer MLP, raw-embedding gather version.
//
// R7 post-mortem: A/B-table gather (512 B/edge, 32 divergent LDG.128) was
// L1tex-wavefront bound (~1024 wf/warp). Now gather raw 64 B embeddings
// (8 LDG.128/edge, 256 wf/warp) and compute layer 1 per edge with packed
// fma.rn.f32x2. All weights live in SMEM as uniform (broadcast) loads.
//   layer1: 1024 fma2  (feats[32] @ W1[32,64], j-paired)
//   layer2+3 fused: 1024 fma2 (h1[64] @ W2[64,32], k-paired) + dot W3
// edge_index output write is fused (indices already in registers).
// ---------------------------------------------------------------------------

typedef unsigned long long u64;

__device__ float g_W2T[32 * 64];          // W2 transposed: [j][k], k contiguous

// ---- f32x2 helpers --------------------------------------------------------
__device__ __forceinline__ u64 pack2(float lo, float hi) {
    u64 r;
    asm("mov.b64 %0, {%1, %2};" : "=l"(r) : "f"(lo), "f"(hi));
    return r;
}
__device__ __forceinline__ float2 unpack2(u64 v) {
    float lo, hi;
    asm("mov.b64 {%0, %1}, %2;" : "=f"(lo), "=f"(hi) : "l"(v));
    return make_float2(lo, hi);
}
__device__ __forceinline__ u64 fma2(u64 a, u64 b, u64 c) {
    u64 d;
    asm("fma.rn.f32x2 %0, %1, %2, %3;" : "=l"(d) : "l"(a), "l"(b), "l"(c));
    return d;
}
__device__ __forceinline__ u64 add2(u64 a, u64 b) {
    u64 d;
    asm("add.rn.f32x2 %0, %1, %2;" : "=l"(d) : "l"(a), "l"(b));
    return d;
}

// ---- prep: transpose W2 (64x32 row-major) -> W2T (32 rows of 64 k-vals) ---
__global__ void prep_w2(const float* __restrict__ W2) {
    int i = blockIdx.x * blockDim.x + threadIdx.x;
    if (i < 64 * 32) {
        int k = i >> 5;       // 0..63
        int j = i & 31;       // 0..31
        g_W2T[j * 64 + k] = W2[i];
    }
}

// ---- main: per-edge fused 3-layer MLP -------------------------------------
__global__ __launch_bounds__(256, 2)
void edge_mlp(const float* __restrict__ emb,
              const int* __restrict__ ei,
              const float* __restrict__ W1,
              const float* __restrict__ b1,
              const float* __restrict__ b2,
              const float* __restrict__ W3,
              const float* __restrict__ b3,
              float* __restrict__ out,
              int E, int write_idx) {
    // W1 rows as j-pairs: sW1[k*32 + j2] = (W1[k][2j2], W1[k][2j2+1])
    __shared__ u64 sW1[32 * 32];          // 8 KB (raw bits of W1, j contiguous)
    __shared__ ulonglong2 sW2[32 * 16];   // 8 KB: col j as 16B k-chunks
    __shared__ u64 sb1[32];               // b1 as j-pairs
    __shared__ float sb2[32];
    __shared__ float sW3[32];
    __shared__ float sb3s;

    {
        const u64* w1u = reinterpret_cast<const u64*>(W1);
        for (int i = threadIdx.x; i < 32 * 32; i += blockDim.x) sW1[i] = w1u[i];
        float4* dst = reinterpret_cast<float4*>(sW2);
        const float4* src = reinterpret_cast<const float4*>(g_W2T);
        for (int i = threadIdx.x; i < 512; i += blockDim.x) dst[i] = src[i];
        if (threadIdx.x < 32) {
            sb1[threadIdx.x] = reinterpret_cast<const u64*>(b1)[threadIdx.x];
            sb2[threadIdx.x] = b2[threadIdx.x];
            sW3[threadIdx.x] = W3[threadIdx.x];
        }
        if (threadIdx.x == 0) sb3s = b3[0];
    }
    __syncthreads();

    int e = blockIdx.x * blockDim.x + threadIdx.x;
    if (e >= E) return;

    int sn = ei[e];
    int dn = ei[E + e];

    // gather raw embeddings: 2 x 64 B, each row = exactly one 128B-line class
    const float4* sp = reinterpret_cast<const float4*>(emb) + (size_t)sn * 4;
    const float4* dp = reinterpret_cast<const float4*>(emb) + (size_t)dn * 4;
    float ff[16], gg[16];
#pragma unroll
    for (int i = 0; i < 4; i++) {
        float4 v = __ldg(sp + i);
        ff[4 * i] = v.x; ff[4 * i + 1] = v.y; ff[4 * i + 2] = v.z; ff[4 * i + 3] = v.w;
    }
#pragma unroll
    for (int i = 0; i < 4; i++) {
        float4 v = __ldg(dp + i);
        gg[4 * i] = v.x; gg[4 * i + 1] = v.y; gg[4 * i + 2] = v.z; gg[4 * i + 3] = v.w;
    }

    // ---- layer 1: acc[j2] = b1-pair + sum_k feats[k] * W1[k][j-pair] ------
    u64 acc[32];
#pragma unroll
    for (int t = 0; t < 32; t++) acc[t] = sb1[t];

#pragma unroll 4
    for (int k = 0; k < 16; k++) {
        u64 fp = pack2(ff[k], ff[k]);
        const ulonglong2* w = reinterpret_cast<const ulonglong2*>(&sW1[k * 32]);
#pragma unroll
        for (int t = 0; t < 16; t++) {
            ulonglong2 wv = w[t];
            acc[2 * t]     = fma2(fp, wv.x, acc[2 * t]);
            acc[2 * t + 1] = fma2(fp, wv.y, acc[2 * t + 1]);
        }
    }
#pragma unroll 4
    for (int k = 0; k < 16; k++) {
        u64 fp = pack2(gg[k], gg[k]);
        const ulonglong2* w = reinterpret_cast<const ulonglong2*>(&sW1[(16 + k) * 32]);
#pragma unroll
        for (int t = 0; t < 16; t++) {
            ulonglong2 wv = w[t];
            acc[2 * t]     = fma2(fp, wv.x, acc[2 * t]);
            acc[2 * t + 1] = fma2(fp, wv.y, acc[2 * t + 1]);
        }
    }

    // relu (pairwise) — acc now holds h1 as k-pairs for layer 2
#pragma unroll
    for (int t = 0; t < 32; t++) {
        float2 v = unpack2(acc[t]);
        acc[t] = pack2(fmaxf(v.x, 0.f), fmaxf(v.y, 0.f));
    }

    // ---- layer 2 + fused layer 3 ------------------------------------------
    float oacc = sb3s;
#pragma unroll 1
    for (int j = 0; j < 32; j += 2) {
        u64 a0 = 0ull, a1 = 0ull, a2 = 0ull, a3 = 0ull;
        const ulonglong2* w0 = &sW2[(j + 0) * 16];
        const ulonglong2* w1 = &sW2[(j + 1) * 16];
#pragma unroll
        for (int q = 0; q < 16; q += 2) {
            ulonglong2 wa = w0[q];
            ulonglong2 wb = w0[q + 1];
            a0 = fma2(acc[2 * q + 0], wa.x, a0);
            a1 = fma2(acc[2 * q + 1], wa.y, a1);
            a0 = fma2(acc[2 * q + 2], wb.x, a0);
            a1 = fma2(acc[2 * q + 3], wb.y, a1);
            ulonglong2 wc = w1[q];
            ulonglong2 wd = w1[q + 1];
            a2 = fma2(acc[2 * q + 0], wc.x, a2);
            a3 = fma2(acc[2 * q + 1], wc.y, a3);
            a2 = fma2(acc[2 * q + 2], wd.x, a2);
            a3 = fma2(acc[2 * q + 3], wd.y, a3);
        }
        float2 s0 = unpack2(add2(a0, a1));
        float2 s1 = unpack2(add2(a2, a3));
        float h2a = fmaxf(s0.x + s0.y + sb2[j + 0], 0.f);
        float h2b = fmaxf(s1.x + s1.y + sb2[j + 1], 0.f);
        oacc = fmaf(h2a, sW3[j + 0], oacc);
        oacc = fmaf(h2b, sW3[j + 1], oacc);
    }

    // sigmoid (fast-math; tolerance 1e-3, measured margin was 5e-8)
    out[e] = __fdividef(1.0f, 1.0f + __expf(-oacc));

    // fused second output: edge_index value-cast (indices already in regs)
    if (write_idx) {
        out[E + e]     = (float)sn;
        out[2 * E + e] = (float)dn;
    }
}

// ---------------------------------------------------------------------------
extern "C" void kernel_launch(void* const* d_in, const int* in_sizes, int n_in,
                              void* d_out, int out_size) {
    const float* emb = (const float*)d_in[0];   // [N_NODES, 16]
    const int*   ei  = (const int*)  d_in[1];   // [2, E]
    const float* W1  = (const float*)d_in[2];   // [32, 64]
    const float* b1  = (const float*)d_in[3];   // [64]
    const float* W2  = (const float*)d_in[4];   // [64, 32]
    const float* b2  = (const float*)d_in[5];   // [32]
    const float* W3  = (const float*)d_in[6];   // [32, 1]
    const float* b3  = (const float*)d_in[7];   // [1]

    int E = in_sizes[1] / 2;
    float* out = (float*)d_out;
    int write_idx = (out_size >= 3 * E) ? 1 : 0;

    prep_w2<<<(64 * 32 + 255) / 256, 256>>>(W2);
    edge_mlp<<<(E + 255) / 256, 256>>>(emb, ei, W1, b1, b2, W3, b3, out, E, write_idx);
}

// round 14
// speedup vs baseline: 1.6154x; 1.6154x over previous
#include <cuda_runtime.h>
#include <cstdint>

// ---------------------------------------------------------------------------
// EdgeDecoder R13: A/B factorization (halves per-edge FLOPs) + warp-
// cooperative gather (fixes R7's 8x L1tex wavefront inflation) + in-flight
// relu(A+B) staging of h1 into SMEM (kills R12's 640-LDS weight streaming).
//
// R12 profile: L1=93.9% (binder), fma=40.5%, occ=22.6%. Causes: (1) 640
// uniform LDS/thread streaming W1+W2, (2) 2048 fma2/edge after dropping the
// A/B precompute (620us fma floor alone), (3) 128-reg spills.
// ---------------------------------------------------------------------------

typedef unsigned long long u64;

#define MAX_NODES 100000

__device__ float g_A[MAX_NODES * 64];     // emb @ W1a            (25.6 MB)
__device__ float g_B[MAX_NODES * 64];     // emb @ W1b + b1       (25.6 MB)
__device__ float g_W2T[32 * 64];          // W2 transposed [j][k]

// ---- f32x2 helpers --------------------------------------------------------
__device__ __forceinline__ u64 pack2(float lo, float hi) {
    u64 r;
    asm("mov.b64 %0, {%1, %2};" : "=l"(r) : "f"(lo), "f"(hi));
    return r;
}
__device__ __forceinline__ float2 unpack2(u64 v) {
    float lo, hi;
    asm("mov.b64 {%0, %1}, %2;" : "=f"(lo), "=f"(hi) : "l"(v));
    return make_float2(lo, hi);
}
__device__ __forceinline__ u64 fma2(u64 a, u64 b, u64 c) {
    u64 d;
    asm("fma.rn.f32x2 %0, %1, %2, %3;" : "=l"(d) : "l"(a), "l"(b), "l"(c));
    return d;
}
__device__ __forceinline__ u64 add2(u64 a, u64 b) {
    u64 d;
    asm("add.rn.f32x2 %0, %1, %2;" : "=l"(d) : "l"(a), "l"(b));
    return d;
}

// ---- prep: transpose W2 (64x32 row-major) -> W2T (32 rows of 64 k-vals) ---
__global__ void prep_w2(const float* __restrict__ W2) {
    int i = blockIdx.x * blockDim.x + threadIdx.x;
    if (i < 64 * 32) {
        int k = i >> 5;
        int j = i & 31;
        g_W2T[j * 64 + k] = W2[i];
    }
}

// ---- prep: per-node A = emb@W1a, B = emb@W1b + b1 -------------------------
__global__ void prep_ab(const float* __restrict__ emb,
                        const float* __restrict__ W1,
                        const float* __restrict__ b1,
                        int n_nodes) {
    __shared__ float sW1[32 * 64];
    __shared__ float sb1[64];
    for (int i = threadIdx.x; i < 32 * 64; i += blockDim.x) sW1[i] = W1[i];
    for (int i = threadIdx.x; i < 64; i += blockDim.x)      sb1[i] = b1[i];
    __syncthreads();

    int n = blockIdx.x * blockDim.x + threadIdx.x;
    if (n >= n_nodes) return;

    float e[16];
    const float4* e4 = reinterpret_cast<const float4*>(emb + (size_t)n * 16);
#pragma unroll
    for (int i = 0; i < 4; i++) {
        float4 v = e4[i];
        e[4 * i + 0] = v.x; e[4 * i + 1] = v.y;
        e[4 * i + 2] = v.z; e[4 * i + 3] = v.w;
    }

    float* Arow = g_A + (size_t)n * 64;
    float* Brow = g_B + (size_t)n * 64;
#pragma unroll 4
    for (int j = 0; j < 64; j++) {
        float a = 0.f, b = 0.f;
#pragma unroll
        for (int k = 0; k < 16; k++) {
            a = fmaf(e[k], sW1[k * 64 + j], a);
            b = fmaf(e[k], sW1[(16 + k) * 64 + j], b);
        }
        Arow[j] = a;
        Brow[j] = b + sb1[j];
    }
}

// ---- main: cooperative gather + fused layer 2/3 ---------------------------
#define NWARP 4
#define H1STRIDE 17   // 16 float4 chunks + 1 pad -> bank spread (lane+c) mod 8

__global__ __launch_bounds__(128, 4)
void edge_mlp(const int* __restrict__ ei,
              const float* __restrict__ b2,
              const float* __restrict__ W3,
              const float* __restrict__ b3,
              float* __restrict__ out,
              int E, int write_idx) {
    __shared__ float4 sH1[NWARP][32][H1STRIDE];   // 34,816 B
    __shared__ ulonglong2 sW2[32 * 16];           // 8 KB: col j as 16B k-chunks
    __shared__ float sb2[32];
    __shared__ float sW3[32];
    __shared__ float sb3s;

    int tid  = threadIdx.x;
    int w    = tid >> 5;
    int lane = tid & 31;

    {
        float4* dst = reinterpret_cast<float4*>(sW2);
        const float4* src = reinterpret_cast<const float4*>(g_W2T);
        for (int i = tid; i < 512; i += blockDim.x) dst[i] = src[i];
        if (tid < 32) {
            sb2[tid] = b2[tid];
            sW3[tid] = W3[tid];
        }
        if (tid == 0) sb3s = b3[0];
    }
    __syncthreads();

    int ebase = blockIdx.x * 128 + w * 32;
    int e = ebase + lane;
    int sn = 0, dn = 0;
    if (e < E) { sn = ei[e]; dn = ei[E + e]; }

    // --- warp-cooperative gather + in-flight relu(A+B) staging -------------
    // Instruction m: lanes cover rows {2m, 2m+1} (16 lanes each), chunk=lane&15.
    // Each 512B warp-load touches exactly 4 x 128B lines -> 4 wf/edge total.
    const float4* A4 = reinterpret_cast<const float4*>(g_A);
    const float4* B4 = reinterpret_cast<const float4*>(g_B);
#pragma unroll
    for (int m = 0; m < 16; m++) {
        int r = 2 * m + (lane >> 4);
        int c = lane & 15;
        int asrc = __shfl_sync(0xffffffffu, sn, r);
        int bdst = __shfl_sync(0xffffffffu, dn, r);
        float4 a = __ldg(A4 + (size_t)asrc * 16 + c);
        float4 b = __ldg(B4 + (size_t)bdst * 16 + c);
        float4 v;
        v.x = fmaxf(a.x + b.x, 0.f);
        v.y = fmaxf(a.y + b.y, 0.f);
        v.z = fmaxf(a.z + b.z, 0.f);
        v.w = fmaxf(a.w + b.w, 0.f);
        sH1[w][r][c] = v;
    }
    __syncwarp();

    if (e >= E) return;

    // --- load this edge's h1 (conflict-free: unit = (lane+c) mod 8) --------
    u64 h1[32];
#pragma unroll
    for (int c = 0; c < 16; c++) {
        float4 v = sH1[w][lane][c];
        h1[2 * c]     = pack2(v.x, v.y);
        h1[2 * c + 1] = pack2(v.z, v.w);
    }

    // --- layer 2 + fused layer 3: 2 cols per iter, 4 fma2 chains -----------
    float oacc = sb3s;
#pragma unroll 1
    for (int j = 0; j < 32; j += 2) {
        u64 a0 = 0ull, a1 = 0ull, a2 = 0ull, a3 = 0ull;
        const ulonglong2* w0 = &sW2[(j + 0) * 16];
        const ulonglong2* w1 = &sW2[(j + 1) * 16];
#pragma unroll
        for (int q = 0; q < 16; q += 2) {
            ulonglong2 wa = w0[q];
            ulonglong2 wb = w0[q + 1];
            a0 = fma2(h1[2 * q + 0], wa.x, a0);
            a1 = fma2(h1[2 * q + 1], wa.y, a1);
            a0 = fma2(h1[2 * q + 2], wb.x, a0);
            a1 = fma2(h1[2 * q + 3], wb.y, a1);
            ulonglong2 wc = w1[q];
            ulonglong2 wd = w1[q + 1];
            a2 = fma2(h1[2 * q + 0], wc.x, a2);
            a3 = fma2(h1[2 * q + 1], wc.y, a3);
            a2 = fma2(h1[2 * q + 2], wd.x, a2);
            a3 = fma2(h1[2 * q + 3], wd.y, a3);
        }
        float2 s0 = unpack2(add2(a0, a1));
        float2 s1 = unpack2(add2(a2, a3));
        float h2a = fmaxf(s0.x + s0.y + sb2[j + 0], 0.f);
        float h2b = fmaxf(s1.x + s1.y + sb2[j + 1], 0.f);
        oacc = fmaf(h2a, sW3[j + 0], oacc);
        oacc = fmaf(h2b, sW3[j + 1], oacc);
    }

    out[e] = __fdividef(1.0f, 1.0f + __expf(-oacc));

    if (write_idx) {
        out[E + e]     = (float)sn;
        out[2 * E + e] = (float)dn;
    }
}

// ---------------------------------------------------------------------------
extern "C" void kernel_launch(void* const* d_in, const int* in_sizes, int n_in,
                              void* d_out, int out_size) {
    const float* emb = (const float*)d_in[0];   // [N_NODES, 16]
    const int*   ei  = (const int*)  d_in[1];   // [2, E]
    const float* W1  = (const float*)d_in[2];   // [32, 64]
    const float* b1  = (const float*)d_in[3];   // [64]
    const float* W2  = (const float*)d_in[4];   // [64, 32]
    const float* b2  = (const float*)d_in[5];   // [32]
    const float* W3  = (const float*)d_in[6];   // [32, 1]
    const float* b3  = (const float*)d_in[7];   // [1]

    int n_nodes = in_sizes[0] / 16;
    int E       = in_sizes[1] / 2;
    float* out  = (float*)d_out;
    int write_idx = (out_size >= 3 * E) ? 1 : 0;

    prep_w2<<<(64 * 32 + 255) / 256, 256>>>(W2);
    prep_ab<<<(n_nodes + 127) / 128, 128>>>(emb, W1, b1, n_nodes);
    edge_mlp<<<(E + 127) / 128, 128>>>(ei, b2, W3, b3, out, E, write_idx);
}